// round 2
// baseline (speedup 1.0000x reference)
#include <cuda_runtime.h>
#include <math.h>

#define Bb     8
#define NN     4096        // H*W
#define RR     32768       // B*NN
#define DD     256
#define D2     512
#define HEADS  8
#define DK     32
#define EPS    1e-5f

// ---------------- scratch (static device globals; no runtime allocation) ----
__device__ float g_tmp1 [RR * DD];            // x1@W1 + b1
__device__ float g_n1   [RR * DD];            // LN(tmp1)
__device__ float g_n2   [RR * DD];            // LN(x2)
__device__ float g_att  [RR * DD];            // attended values per token
__device__ float g_tmp2 [RR * D2];            // reproj output pre-LN
__device__ float g_Wt   [DD * D2];            // reproj_w transposed [c][o]
__device__ float g_part [Bb * 8 * DD];        // ksum partials per chunk
__device__ float g_ksum [Bb * DD];            // token-softmax denominators
__device__ float g_Spart[8 * Bb * HEADS * DK * DK]; // ctx partials per chunk
__device__ float g_ctx  [Bb * HEADS * DK * DK];

// ---------------- SGEMM: C[M,N] = A[M,K] @ B[K,N] (+bias[N]) -----------------
// BM=BN=128, BK=8, 256 threads, 8x8 register tile per thread.
// M % 128 == 0, N % 128 == 0, K % 8 == 0 guaranteed by the shapes here.
#define BM 128
#define BN 128
#define BK 8
#define TM 8
#define TN 8

__global__ __launch_bounds__(256) void sgemm_bias_k(
    const float* __restrict__ A, const float* __restrict__ B,
    const float* __restrict__ bias, float* __restrict__ C,
    int M, int N, int K)
{
    __shared__ __align__(16) float As[BK][BM];
    __shared__ __align__(16) float Bs[BK][BN];

    const int t  = threadIdx.x;
    const int m0 = blockIdx.y * BM;
    const int n0 = blockIdx.x * BN;

    const int aRow = t >> 1;            // 0..127
    const int aCol = (t & 1) * 4;       // 0 or 4
    const int bRow = t >> 5;            // 0..7
    const int bCol = (t & 31) * 4;      // 0..124

    const int tx = t & 15;              // col group
    const int ty = t >> 4;              // row group

    float acc[TM][TN];
#pragma unroll
    for (int i = 0; i < TM; i++)
#pragma unroll
        for (int j = 0; j < TN; j++) acc[i][j] = 0.f;

    const float* Aptr = A + (size_t)(m0 + aRow) * K + aCol;
    const float* Bptr = B + (size_t)bRow * N + n0 + bCol;

    for (int k0 = 0; k0 < K; k0 += BK) {
        float4 av = *(const float4*)(Aptr + k0);
        float4 bv = *(const float4*)(Bptr + (size_t)k0 * N);
        As[aCol + 0][aRow] = av.x;
        As[aCol + 1][aRow] = av.y;
        As[aCol + 2][aRow] = av.z;
        As[aCol + 3][aRow] = av.w;
        *(float4*)&Bs[bRow][bCol] = bv;
        __syncthreads();

#pragma unroll
        for (int kk = 0; kk < BK; kk++) {
            float af[TM], bf[TN];
            *(float4*)&af[0] = *(const float4*)&As[kk][ty * TM];
            *(float4*)&af[4] = *(const float4*)&As[kk][ty * TM + 4];
            *(float4*)&bf[0] = *(const float4*)&Bs[kk][tx * TN];
            *(float4*)&bf[4] = *(const float4*)&Bs[kk][tx * TN + 4];
#pragma unroll
            for (int i = 0; i < TM; i++)
#pragma unroll
                for (int j = 0; j < TN; j++)
                    acc[i][j] += af[i] * bf[j];
        }
        __syncthreads();
    }

    float bb[TN];
#pragma unroll
    for (int j = 0; j < TN; j++) bb[j] = bias ? bias[n0 + tx * TN + j] : 0.f;

#pragma unroll
    for (int i = 0; i < TM; i++) {
        const int row = m0 + ty * TM + i;
        float* cp = C + (size_t)row * N + n0 + tx * TN;
        float4 o0, o1;
        o0.x = acc[i][0] + bb[0]; o0.y = acc[i][1] + bb[1];
        o0.z = acc[i][2] + bb[2]; o0.w = acc[i][3] + bb[3];
        o1.x = acc[i][4] + bb[4]; o1.y = acc[i][5] + bb[5];
        o1.z = acc[i][6] + bb[6]; o1.w = acc[i][7] + bb[7];
        *(float4*)cp       = o0;
        *(float4*)(cp + 4) = o1;
    }
}

// ---------------- warp-per-row LayerNorm over D=256 (two sources) ------------
__global__ __launch_bounds__(256) void ln_rows_k(
    const float* __restrict__ s1, const float* __restrict__ s2,
    const float* __restrict__ g, const float* __restrict__ b,
    float* __restrict__ d1, float* __restrict__ d2)
{
    const int gw   = (blockIdx.x * blockDim.x + threadIdx.x) >> 5; // 0..2R-1
    const int lane = threadIdx.x & 31;

    const float* src; float* dst; int row;
    if (gw < RR) { src = s1; dst = d1; row = gw; }
    else         { src = s2; dst = d2; row = gw - RR; }

    const float* p = src + (size_t)row * DD + lane * 8;
    float4 a = *(const float4*)p;
    float4 c = *(const float4*)(p + 4);

    float s = a.x + a.y + a.z + a.w + c.x + c.y + c.z + c.w;
#pragma unroll
    for (int o = 16; o; o >>= 1) s += __shfl_xor_sync(0xffffffffu, s, o);
    const float mean = s * (1.0f / DD);

    float ax = a.x - mean, ay = a.y - mean, az = a.z - mean, aw = a.w - mean;
    float cx = c.x - mean, cy = c.y - mean, cz = c.z - mean, cw = c.w - mean;
    float s2sum = ax*ax + ay*ay + az*az + aw*aw + cx*cx + cy*cy + cz*cz + cw*cw;
#pragma unroll
    for (int o = 16; o; o >>= 1) s2sum += __shfl_xor_sync(0xffffffffu, s2sum, o);
    const float rstd = rsqrtf(s2sum * (1.0f / DD) + EPS);

    const int ci = lane * 8;
    float4 g0 = *(const float4*)(g + ci);
    float4 g1 = *(const float4*)(g + ci + 4);
    float4 b0 = *(const float4*)(b + ci);
    float4 b1 = *(const float4*)(b + ci + 4);

    float4 o0, o1;
    o0.x = ax * rstd * g0.x + b0.x; o0.y = ay * rstd * g0.y + b0.y;
    o0.z = az * rstd * g0.z + b0.z; o0.w = aw * rstd * g0.w + b0.w;
    o1.x = cx * rstd * g1.x + b1.x; o1.y = cy * rstd * g1.y + b1.y;
    o1.z = cz * rstd * g1.z + b1.z; o1.w = cw * rstd * g1.w + b1.w;

    float* q = dst + (size_t)row * DD + ci;
    *(float4*)q       = o0;
    *(float4*)(q + 4) = o1;
}

// ---------------- token-softmax denominators: ksum[b][c] = sum_n exp(n2) -----
__global__ __launch_bounds__(256) void ksum_part_k(
    const float* __restrict__ n2, float* __restrict__ part)
{
    const int chunk = blockIdx.x;   // 8 chunks of 512 tokens
    const int b     = blockIdx.y;
    const int c     = threadIdx.x;  // 256 channels
    const float* p = n2 + ((size_t)b * NN + chunk * 512) * DD + c;
    float s = 0.f;
#pragma unroll 4
    for (int n = 0; n < 512; n++) s += expf(p[(size_t)n * DD]);
    part[(b * 8 + chunk) * DD + c] = s;
}

__global__ void ksum_reduce_k(const float* __restrict__ part,
                              float* __restrict__ ksum)
{
    const int b = blockIdx.x, c = threadIdx.x;
    float s = 0.f;
#pragma unroll
    for (int j = 0; j < 8; j++) s += part[(b * 8 + j) * DD + c];
    ksum[b * DD + c] = s;
}

// ---------------- ctx partials: S[d,e] = sum_n (e_d / qsum_n) * e_e ----------
__global__ __launch_bounds__(256) void ctx_part_k(
    const float* __restrict__ n2, float* __restrict__ Spart)
{
    __shared__ __align__(16) float sm_e[8][32];
    __shared__ __align__(16) float sm_q[8][32];

    const int chunk = blockIdx.x;   // 8
    const int h     = blockIdx.y;   // 8
    const int b     = blockIdx.z;   // 8
    const int t     = threadIdx.x;  // 256
    const int lane  = t & 31;       // channel within head
    const int w     = t >> 5;       // token within 8-batch
    const int tx    = t & 15;       // e group
    const int ty    = t >> 4;       // d group

    float a00 = 0.f, a01 = 0.f, a10 = 0.f, a11 = 0.f;
    const float* base = n2 + ((size_t)b * NN + chunk * 512) * DD + h * DK;

    for (int nb = 0; nb < 512; nb += 8) {
        float e = expf(base[(size_t)(nb + w) * DD + lane]);
        float qs = e;
#pragma unroll
        for (int o = 16; o; o >>= 1) qs += __shfl_xor_sync(0xffffffffu, qs, o);
        sm_e[w][lane] = e;
        sm_q[w][lane] = e / qs;
        __syncthreads();
#pragma unroll
        for (int j = 0; j < 8; j++) {
            float2 qd = *(const float2*)&sm_q[j][ty * 2];
            float2 ke = *(const float2*)&sm_e[j][tx * 2];
            a00 += qd.x * ke.x; a01 += qd.x * ke.y;
            a10 += qd.y * ke.x; a11 += qd.y * ke.y;
        }
        __syncthreads();
    }

    float* o = Spart + (size_t)(chunk * 64 + b * 8 + h) * (DK * DK);
    const int d = ty * 2, e = tx * 2;
    o[d * 32 + e]           = a00;
    o[d * 32 + e + 1]       = a01;
    o[(d + 1) * 32 + e]     = a10;
    o[(d + 1) * 32 + e + 1] = a11;
}

// ---------------- ctx final: reduce chunks, divide by ksum[e] ----------------
__global__ void ctx_final_k(const float* __restrict__ Spart,
                            const float* __restrict__ ksum,
                            float* __restrict__ ctx)
{
    const int bh = blockIdx.x;    // 64 = b*8+h
    const int t  = threadIdx.x;   // 1024 = d*32+e
    const int b  = bh >> 3, h = bh & 7;
    const int e  = t & 31;
    float s = 0.f;
#pragma unroll
    for (int ch = 0; ch < 8; ch++)
        s += Spart[(size_t)(ch * 64 + bh) * (DK * DK) + t];
    ctx[(size_t)bh * (DK * DK) + t] = s / ksum[b * DD + h * DK + e];
}

// ---------------- att[token][c] = sum_e ctx[h(c)][d(c)][e] * n1[token][h*32+e]
__global__ __launch_bounds__(256) void att_k(
    const float* __restrict__ ctx, const float* __restrict__ n1,
    float* __restrict__ att)
{
    __shared__ __align__(16) float ctxs[HEADS * DK * DK]; // 32 KB
    __shared__ float n1s[DD];

    const int chunk = blockIdx.x;  // 64 chunks of 64 tokens
    const int b     = blockIdx.y;
    const int t     = threadIdx.x; // channel c

    const float* csrc = ctx + (size_t)b * HEADS * DK * DK;
    for (int i = t; i < HEADS * DK * DK; i += 256) ctxs[i] = csrc[i];
    __syncthreads();

    const int h = t >> 5, d = t & 31;
    float creg[DK];
#pragma unroll
    for (int e = 0; e < DK; e += 4)
        *(float4*)&creg[e] = *(const float4*)&ctxs[h * DK * DK + d * DK + e];

    const int base = h * DK;
    const size_t row0 = (size_t)b * NN + chunk * 64;
    for (int tok = 0; tok < 64; tok++) {
        __syncthreads();
        n1s[t] = n1[(row0 + tok) * DD + t];
        __syncthreads();
        float a = 0.f;
#pragma unroll
        for (int e = 0; e < DK; e++) a += creg[e] * n1s[base + e];
        att[(row0 + tok) * DD + t] = a;
    }
}

// ---------------- transpose reproj_w [512][256] -> Wt [256][512] -------------
__global__ void transpose_w_k(const float* __restrict__ Wr,
                              float* __restrict__ Wt)
{
    __shared__ float tile[32][33];
    const int c0 = blockIdx.x * 32;  // cols of Wr (256)
    const int o0 = blockIdx.y * 32;  // rows of Wr (512)
    const int x = threadIdx.x, y = threadIdx.y; // 32x8
#pragma unroll
    for (int i = 0; i < 32; i += 8)
        tile[y + i][x] = Wr[(size_t)(o0 + y + i) * DD + c0 + x];
    __syncthreads();
#pragma unroll
    for (int i = 0; i < 32; i += 8)
        Wt[(size_t)(c0 + y + i) * D2 + o0 + x] = tile[x][y + i];
}

// ---------------- final LN(512) + residual add -------------------------------
__global__ __launch_bounds__(128) void final_ln_add_k(
    const float* __restrict__ tmp2, const float* __restrict__ x1,
    const float* __restrict__ g, const float* __restrict__ bt,
    float* __restrict__ outp)
{
    __shared__ float red[8];
    const int row = blockIdx.x;
    const int t   = threadIdx.x; // 128, 4 floats each
    const size_t off = (size_t)row * D2 + t * 4;

    float4 v = *(const float4*)(tmp2 + off);
    float s = v.x + v.y + v.z + v.w;
#pragma unroll
    for (int o = 16; o; o >>= 1) s += __shfl_xor_sync(0xffffffffu, s, o);
    if ((t & 31) == 0) red[t >> 5] = s;
    __syncthreads();
    const float mean = (red[0] + red[1] + red[2] + red[3]) * (1.0f / D2);

    float dx = v.x - mean, dy = v.y - mean, dz = v.z - mean, dw = v.w - mean;
    float s2 = dx * dx + dy * dy + dz * dz + dw * dw;
#pragma unroll
    for (int o = 16; o; o >>= 1) s2 += __shfl_xor_sync(0xffffffffu, s2, o);
    if ((t & 31) == 0) red[4 + (t >> 5)] = s2;
    __syncthreads();
    const float var  = (red[4] + red[5] + red[6] + red[7]) * (1.0f / D2);
    const float rstd = rsqrtf(var + EPS);

    float4 xv = *(const float4*)(x1 + off);
    float4 gg = *(const float4*)(g + t * 4);
    float4 bb = *(const float4*)(bt + t * 4);
    float4 o4;
    o4.x = xv.x + dx * rstd * gg.x + bb.x;
    o4.y = xv.y + dy * rstd * gg.y + bb.y;
    o4.z = xv.z + dz * rstd * gg.z + bb.z;
    o4.w = xv.w + dw * rstd * gg.w + bb.w;
    *(float4*)(outp + off) = o4;
}

// ---------------- host launch ------------------------------------------------
extern "C" void kernel_launch(void* const* d_in, const int* in_sizes, int n_in,
                              void* d_out, int out_size)
{
    const float* x1        = (const float*)d_in[0];
    const float* x2        = (const float*)d_in[1];
    const float* linear_w  = (const float*)d_in[2];
    const float* linear_b  = (const float*)d_in[3];
    const float* ln1_g     = (const float*)d_in[4];
    const float* ln1_b     = (const float*)d_in[5];
    const float* reproj_w  = (const float*)d_in[6];
    const float* reproj_b  = (const float*)d_in[7];
    const float* ln_attn_g = (const float*)d_in[8];
    const float* ln_attn_b = (const float*)d_in[9];
    float* out = (float*)d_out;

    float *tmp1, *n1, *n2, *att, *tmp2, *Wt, *part, *ksum, *Spart, *ctx;
    cudaGetSymbolAddress((void**)&tmp1,  g_tmp1);
    cudaGetSymbolAddress((void**)&n1,    g_n1);
    cudaGetSymbolAddress((void**)&n2,    g_n2);
    cudaGetSymbolAddress((void**)&att,   g_att);
    cudaGetSymbolAddress((void**)&tmp2,  g_tmp2);
    cudaGetSymbolAddress((void**)&Wt,    g_Wt);
    cudaGetSymbolAddress((void**)&part,  g_part);
    cudaGetSymbolAddress((void**)&ksum,  g_ksum);
    cudaGetSymbolAddress((void**)&Spart, g_Spart);
    cudaGetSymbolAddress((void**)&ctx,   g_ctx);

    // 1. transpose reproj weights
    transpose_w_k<<<dim3(DD / 32, D2 / 32), dim3(32, 8)>>>(reproj_w, Wt);
    // 2. GEMM1: tmp1 = x1 @ W1 + b1
    sgemm_bias_k<<<dim3(DD / BN, RR / BM), 256>>>(x1, linear_w, linear_b, tmp1,
                                                  RR, DD, D2);
    // 3. LN rows: n1 = LN(tmp1), n2 = LN(x2)
    ln_rows_k<<<(2 * RR / 8), 256>>>(tmp1, x2, ln1_g, ln1_b, n1, n2);
    // 4. token-softmax denominators
    ksum_part_k<<<dim3(8, Bb), 256>>>(n2, part);
    ksum_reduce_k<<<Bb, DD>>>(part, ksum);
    // 5. ctx = (q @ k^T) per (b,h)
    ctx_part_k<<<dim3(8, HEADS, Bb), 256>>>(n2, Spart);
    ctx_final_k<<<Bb * HEADS, DK * DK>>>(Spart, ksum, ctx);
    // 6. att = blockdiag(ctx) @ n1 per token
    att_k<<<dim3(64, Bb), 256>>>(ctx, n1, att);
    // 7. GEMM2: tmp2 = att @ Wt + reproj_b
    sgemm_bias_k<<<dim3(D2 / BN, RR / BM), 256>>>(att, Wt, reproj_b, tmp2,
                                                  RR, D2, DD);
    // 8. out = x1 + LN(tmp2)
    final_ln_add_k<<<RR, 128>>>(tmp2, x1, ln_attn_g, ln_attn_b, out);
}

// round 4
// speedup vs baseline: 1.9686x; 1.9686x over previous
#include <cuda_runtime.h>
#include <cuda_bf16.h>
#include <cstdint>
#include <math.h>

#define Bb     8
#define NN     4096
#define RR     32768
#define DD     256
#define D2     512
#define HEADS  8
#define DK     32
#define EPS    1e-5f

// ---------------- scratch (device globals; no runtime allocation) -----------
__device__ float         g_tmp1[RR * DD];
__device__ float         g_n1  [RR * DD];
__device__ float         g_n2  [RR * DD];
__device__ float         g_tmp2[RR * D2];
__device__ __nv_bfloat16 g_w1h [DD * D2];       // W1^T hi  [n][k]
__device__ __nv_bfloat16 g_w1l [DD * D2];       // W1^T lo
__device__ __nv_bfloat16 g_b2h [Bb * D2 * DD];  // W2eff hi [b][o][c]
__device__ __nv_bfloat16 g_b2l [Bb * D2 * DD];
__device__ float         g_part [Bb * 8 * DD];
__device__ float         g_ksum [Bb * DD];
__device__ float         g_Spart[8 * Bb * HEADS * DK * DK];
__device__ float         g_ctx  [Bb * HEADS * DK * DK];

// ---------------- helpers ----------------------------------------------------
__device__ __forceinline__ uint32_t s2u(const void* p) {
    uint32_t a;
    asm("{ .reg .u64 t; cvta.to.shared.u64 t, %1; cvt.u32.u64 %0, t; }"
        : "=r"(a) : "l"(p));
    return a;
}

__device__ __forceinline__ void split4(float4 v, uint2& hi, uint2& lo) {
    __nv_bfloat162 ha = __floats2bfloat162_rn(v.x, v.y);
    __nv_bfloat162 hb = __floats2bfloat162_rn(v.z, v.w);
    __nv_bfloat162 la = __floats2bfloat162_rn(v.x - __low2float(ha),
                                              v.y - __high2float(ha));
    __nv_bfloat162 lb = __floats2bfloat162_rn(v.z - __low2float(hb),
                                              v.w - __high2float(hb));
    hi.x = *reinterpret_cast<uint32_t*>(&ha);
    hi.y = *reinterpret_cast<uint32_t*>(&hb);
    lo.x = *reinterpret_cast<uint32_t*>(&la);
    lo.y = *reinterpret_cast<uint32_t*>(&lb);
}
__device__ __forceinline__ void split8(const float4& v0, const float4& v1,
                                       uint4& hi, uint4& lo) {
    uint2 h0, l0, h1, l1;
    split4(v0, h0, l0);
    split4(v1, h1, l1);
    hi = make_uint4(h0.x, h0.y, h1.x, h1.y);
    lo = make_uint4(l0.x, l0.y, l1.x, l1.y);
}

__device__ __forceinline__ void ldsm4(uint32_t* r, uint32_t addr) {
    asm volatile("ldmatrix.sync.aligned.m8n8.x4.shared.b16 {%0,%1,%2,%3}, [%4];"
                 : "=r"(r[0]), "=r"(r[1]), "=r"(r[2]), "=r"(r[3]) : "r"(addr));
}
__device__ __forceinline__ void mma16816(float* c, const uint32_t* a,
                                         const uint32_t* b) {
    asm volatile(
        "mma.sync.aligned.m16n8k16.row.col.f32.bf16.bf16.f32 "
        "{%0,%1,%2,%3}, {%4,%5,%6,%7}, {%8,%9}, {%0,%1,%2,%3};"
        : "+f"(c[0]), "+f"(c[1]), "+f"(c[2]), "+f"(c[3])
        : "r"(a[0]), "r"(a[1]), "r"(a[2]), "r"(a[3]), "r"(b[0]), "r"(b[1]));
}

// swizzled byte offset: rows of 32 bf16 (64B), 4 chunks of 16B, XOR swizzle
__device__ __forceinline__ uint32_t sw_off(int row, int cch) {
    return (uint32_t)(row * 64 + ((cch ^ ((row >> 1) & 3)) << 4));
}

// ---------------- bf16 split-compensated HMMA GEMM ---------------------------
// C[M,N] = A[M,K](fp32) @ B[N,K](bf16 hi/lo, row-major n x k) + bias[N]
// CTA 128x128, 8 warps (2 m-groups x 4 n-groups), warp tile 64x32, KC=32.
__global__ __launch_bounds__(256, 2) void mma_gemm_k(
    const float* __restrict__ A, const __nv_bfloat16* __restrict__ Bh,
    const __nv_bfloat16* __restrict__ Bl, const float* __restrict__ bias,
    float* __restrict__ C, int K, int N, int rows_per_batch, int bstride)
{
    __shared__ __align__(16) __nv_bfloat16 sAh[128 * 32];
    __shared__ __align__(16) __nv_bfloat16 sAl[128 * 32];
    __shared__ __align__(16) __nv_bfloat16 sBh[128 * 32];
    __shared__ __align__(16) __nv_bfloat16 sBl[128 * 32];

    const int t = threadIdx.x, lane = t & 31, wid = t >> 5;
    const int wm = (wid & 1) * 64;       // warp row offset
    const int wn = (wid >> 1) * 32;      // warp col offset
    const int row0 = blockIdx.y * 128, n0 = blockIdx.x * 128;
    const int b = row0 / rows_per_batch;
    const __nv_bfloat16* bhp = Bh + (size_t)b * bstride;
    const __nv_bfloat16* blp = Bl + (size_t)b * bstride;

    const uint32_t uAh = s2u(sAh), uAl = s2u(sAl);
    const uint32_t uBh = s2u(sBh), uBl = s2u(sBl);

    float acc[4][4][4];
#pragma unroll
    for (int i = 0; i < 4; i++)
#pragma unroll
        for (int j = 0; j < 4; j++)
#pragma unroll
            for (int k = 0; k < 4; k++) acc[i][j][k] = 0.f;

    // staging: thread t loads row (t>>1), 16 cols at (t&1)*16
    const int ar = t >> 1, acol = (t & 1) * 16;
    const float*         aptr  = A   + (size_t)(row0 + ar) * K + acol;
    const __nv_bfloat16* bhptr = bhp + (size_t)(n0 + ar) * K + acol;
    const __nv_bfloat16* blptr = blp + (size_t)(n0 + ar) * K + acol;
    const uint32_t sta0 = sw_off(ar, (acol >> 3));
    const uint32_t sta1 = sw_off(ar, (acol >> 3) + 1);

    // lane-constant pieces of ldmatrix addressing
    const int ti = lane >> 3, tr = lane & 7;
    const int a_dm  = (ti & 1) * 8, a_dkc = ti >> 1;   // A tile: (dm, dk chunk)
    const int b_dn  = (ti >> 1) * 8, b_dkc = ti & 1;   // B tile: (dn, dk chunk)

    const int nk = K >> 5;
    for (int kk = 0; kk < nk; kk++) {
        const int k0 = kk << 5;
        float4 a0 = *(const float4*)(aptr + k0);
        float4 a1 = *(const float4*)(aptr + k0 + 4);
        float4 a2 = *(const float4*)(aptr + k0 + 8);
        float4 a3 = *(const float4*)(aptr + k0 + 12);
        uint4 bh0 = *(const uint4*)(bhptr + k0);
        uint4 bh1 = *(const uint4*)(bhptr + k0 + 8);
        uint4 bl0 = *(const uint4*)(blptr + k0);
        uint4 bl1 = *(const uint4*)(blptr + k0 + 8);
        uint4 ah0, al0, ah1, al1;
        split8(a0, a1, ah0, al0);
        split8(a2, a3, ah1, al1);

        __syncthreads();
        *(uint4*)((char*)sAh + sta0) = ah0;
        *(uint4*)((char*)sAh + sta1) = ah1;
        *(uint4*)((char*)sAl + sta0) = al0;
        *(uint4*)((char*)sAl + sta1) = al1;
        *(uint4*)((char*)sBh + sta0) = bh0;
        *(uint4*)((char*)sBh + sta1) = bh1;
        *(uint4*)((char*)sBl + sta0) = bl0;
        *(uint4*)((char*)sBl + sta1) = bl1;
        __syncthreads();

#pragma unroll
        for (int ks = 0; ks < 2; ks++) {
            uint32_t af[4][4], bf[2][4], bf2[2][4];
#pragma unroll
            for (int mf = 0; mf < 4; mf++) {
                const int row = wm + mf * 16 + a_dm + tr;
                ldsm4(af[mf], uAh + sw_off(row, ks * 2 + a_dkc));
            }
#pragma unroll
            for (int g = 0; g < 2; g++) {
                const int row = wn + g * 16 + b_dn + tr;
                ldsm4(bf[g], uBh + sw_off(row, ks * 2 + b_dkc));
            }
#pragma unroll
            for (int mf = 0; mf < 4; mf++)
#pragma unroll
                for (int nf = 0; nf < 4; nf++)
                    mma16816(acc[mf][nf], af[mf], &bf[nf >> 1][(nf & 1) * 2]);
#pragma unroll
            for (int g = 0; g < 2; g++) {
                const int row = wn + g * 16 + b_dn + tr;
                ldsm4(bf2[g], uBl + sw_off(row, ks * 2 + b_dkc));
            }
#pragma unroll
            for (int mf = 0; mf < 4; mf++)
#pragma unroll
                for (int nf = 0; nf < 4; nf++)
                    mma16816(acc[mf][nf], af[mf], &bf2[nf >> 1][(nf & 1) * 2]);
#pragma unroll
            for (int mf = 0; mf < 4; mf++) {
                const int row = wm + mf * 16 + a_dm + tr;
                ldsm4(af[mf], uAl + sw_off(row, ks * 2 + a_dkc));
            }
#pragma unroll
            for (int mf = 0; mf < 4; mf++)
#pragma unroll
                for (int nf = 0; nf < 4; nf++)
                    mma16816(acc[mf][nf], af[mf], &bf[nf >> 1][(nf & 1) * 2]);
        }
    }

    // epilogue: + bias, store fp32
    const int rbase = row0 + wm + (lane >> 2);
    const int cbase = n0 + wn + (lane & 3) * 2;
#pragma unroll
    for (int nf = 0; nf < 4; nf++) {
        const int c = cbase + nf * 8;
        const float bx = bias[c], by = bias[c + 1];
#pragma unroll
        for (int mf = 0; mf < 4; mf++) {
            const int r = rbase + mf * 16;
            float2 v0 = make_float2(acc[mf][nf][0] + bx, acc[mf][nf][1] + by);
            float2 v1 = make_float2(acc[mf][nf][2] + bx, acc[mf][nf][3] + by);
            *(float2*)(C + (size_t)r * N + c) = v0;
            *(float2*)(C + (size_t)(r + 8) * N + c) = v1;
        }
    }
}

// ---------------- warp-per-row LayerNorm over D=256 --------------------------
__global__ __launch_bounds__(256) void ln_k(
    const float* __restrict__ src, const float* __restrict__ g,
    const float* __restrict__ b, float* __restrict__ dst)
{
    const int row  = (blockIdx.x * blockDim.x + threadIdx.x) >> 5;
    const int lane = threadIdx.x & 31;
    const float* p = src + (size_t)row * DD + lane * 8;
    float4 a = *(const float4*)p;
    float4 c = *(const float4*)(p + 4);

    float s = a.x + a.y + a.z + a.w + c.x + c.y + c.z + c.w;
#pragma unroll
    for (int o = 16; o; o >>= 1) s += __shfl_xor_sync(0xffffffffu, s, o);
    const float mean = s * (1.0f / DD);

    float ax = a.x - mean, ay = a.y - mean, az = a.z - mean, aw = a.w - mean;
    float cx = c.x - mean, cy = c.y - mean, cz = c.z - mean, cw = c.w - mean;
    float s2 = ax*ax + ay*ay + az*az + aw*aw + cx*cx + cy*cy + cz*cz + cw*cw;
#pragma unroll
    for (int o = 16; o; o >>= 1) s2 += __shfl_xor_sync(0xffffffffu, s2, o);
    const float rstd = rsqrtf(s2 * (1.0f / DD) + EPS);

    const int ci = lane * 8;
    float4 g0 = *(const float4*)(g + ci);
    float4 g1 = *(const float4*)(g + ci + 4);
    float4 b0 = *(const float4*)(b + ci);
    float4 b1 = *(const float4*)(b + ci + 4);
    float4 o0, o1;
    o0.x = ax*rstd*g0.x + b0.x; o0.y = ay*rstd*g0.y + b0.y;
    o0.z = az*rstd*g0.z + b0.z; o0.w = aw*rstd*g0.w + b0.w;
    o1.x = cx*rstd*g1.x + b1.x; o1.y = cy*rstd*g1.y + b1.y;
    o1.z = cz*rstd*g1.z + b1.z; o1.w = cw*rstd*g1.w + b1.w;
    float* q = dst + (size_t)row * DD + ci;
    *(float4*)q       = o0;
    *(float4*)(q + 4) = o1;
}

// ---------------- ctx partials + fused ksum partials -------------------------
__global__ __launch_bounds__(256) void ctx_part_k(
    const float* __restrict__ n2, float* __restrict__ Spart,
    float* __restrict__ part)
{
    __shared__ __align__(16) float sm_e[8][32];
    __shared__ __align__(16) float sm_q[8][32];
    __shared__ float sred[8][32];

    const int chunk = blockIdx.x;   // 8
    const int h     = blockIdx.y;   // 8
    const int b     = blockIdx.z;   // 8
    const int t     = threadIdx.x;
    const int lane  = t & 31;
    const int w     = t >> 5;
    const int tx    = t & 15;
    const int ty    = t >> 4;

    float a00 = 0.f, a01 = 0.f, a10 = 0.f, a11 = 0.f, ks = 0.f;
    const float* base = n2 + ((size_t)b * NN + chunk * 512) * DD + h * DK;

    for (int nb = 0; nb < 512; nb += 8) {
        float e = expf(base[(size_t)(nb + w) * DD + lane]);
        ks += e;
        float qs = e;
#pragma unroll
        for (int o = 16; o; o >>= 1) qs += __shfl_xor_sync(0xffffffffu, qs, o);
        sm_e[w][lane] = e;
        sm_q[w][lane] = e / qs;
        __syncthreads();
#pragma unroll
        for (int j = 0; j < 8; j++) {
            float2 qd = *(const float2*)&sm_q[j][ty * 2];
            float2 ke = *(const float2*)&sm_e[j][tx * 2];
            a00 += qd.x * ke.x; a01 += qd.x * ke.y;
            a10 += qd.y * ke.x; a11 += qd.y * ke.y;
        }
        __syncthreads();
    }

    sred[w][lane] = ks;
    __syncthreads();
    if (t < 32) {
        float s = 0.f;
#pragma unroll
        for (int j = 0; j < 8; j++) s += sred[j][t];
        part[(b * 8 + chunk) * DD + h * DK + t] = s;
    }

    float* o = Spart + (size_t)(chunk * 64 + b * 8 + h) * (DK * DK);
    const int d = ty * 2, e = tx * 2;
    o[d * 32 + e]           = a00;
    o[d * 32 + e + 1]       = a01;
    o[(d + 1) * 32 + e]     = a10;
    o[(d + 1) * 32 + e + 1] = a11;
}

__global__ void ksum_reduce_k(const float* __restrict__ part,
                              float* __restrict__ ksum)
{
    const int b = blockIdx.x, c = threadIdx.x;
    float s = 0.f;
#pragma unroll
    for (int j = 0; j < 8; j++) s += part[(b * 8 + j) * DD + c];
    ksum[b * DD + c] = s;
}

__global__ __launch_bounds__(1024) void ctx_final_k(
    const float* __restrict__ Spart, const float* __restrict__ ksum,
    float* __restrict__ ctx)
{
    const int bh = blockIdx.x;
    const int t  = threadIdx.x;   // d*32+e
    const int b  = bh >> 3, h = bh & 7;
    const int e  = t & 31;
    float s = 0.f;
#pragma unroll
    for (int ch = 0; ch < 8; ch++)
        s += Spart[(size_t)(ch * 64 + bh) * (DK * DK) + t];
    ctx[(size_t)bh * (DK * DK) + t] = s / ksum[b * DD + h * DK + e];
}

// ---------------- W2eff[b][o][c=h*32+e] = sum_d ctx[b,h,d,e]*rw[o][h*32+d] ---
__global__ __launch_bounds__(256) void w2eff_k(
    const float* __restrict__ ctx, const float* __restrict__ rw,
    __nv_bfloat16* __restrict__ b2h, __nv_bfloat16* __restrict__ b2l)
{
    extern __shared__ float ws[];
    float* ctxs = ws;          // 8192
    float* rws  = ws + 8192;   // 32 x 256
    const int b  = blockIdx.x;
    const int o0 = blockIdx.y * 32;
    const int t  = threadIdx.x;

    const float* cs = ctx + (size_t)b * HEADS * DK * DK;
    for (int i = t; i < HEADS * DK * DK; i += 256) ctxs[i] = cs[i];
    for (int i = t; i < 32 * 256; i += 256)
        rws[i] = rw[(size_t)(o0 + (i >> 8)) * DD + (i & 255)];
    __syncthreads();

    const int h = t >> 5, e = t & 31;
    const float* cbase = ctxs + h * (DK * DK) + e;
    for (int o = 0; o < 32; o++) {
        float acc = 0.f;
        const float* rb = rws + (o << 8) + h * DK;
#pragma unroll
        for (int d = 0; d < 32; d++) acc += cbase[d * 32] * rb[d];
        size_t off = ((size_t)b * D2 + o0 + o) * DD + t;
        __nv_bfloat16 hh = __float2bfloat16(acc);
        b2h[off] = hh;
        b2l[off] = __float2bfloat16(acc - __bfloat162float(hh));
    }
}

// ---------------- W1 transpose + bf16 hi/lo split ----------------------------
__global__ void convert_w1_k(const float* __restrict__ W,
                             __nv_bfloat16* __restrict__ wh,
                             __nv_bfloat16* __restrict__ wl)
{
    __shared__ float tile[32][33];
    const int n0 = blockIdx.x * 32;   // DD cols of W
    const int k0 = blockIdx.y * 32;   // D2 rows of W
    const int x = threadIdx.x, y = threadIdx.y;  // 32x8
#pragma unroll
    for (int i = 0; i < 32; i += 8)
        tile[y + i][x] = W[(size_t)(k0 + y + i) * DD + n0 + x];
    __syncthreads();
#pragma unroll
    for (int i = 0; i < 32; i += 8) {
        float v = tile[x][y + i];
        __nv_bfloat16 h = __float2bfloat16(v);
        size_t o = (size_t)(n0 + y + i) * D2 + k0 + x;
        wh[o] = h;
        wl[o] = __float2bfloat16(v - __bfloat162float(h));
    }
}

// ---------------- final LN(512) + residual add -------------------------------
__global__ __launch_bounds__(128) void final_ln_add_k(
    const float* __restrict__ tmp2, const float* __restrict__ x1,
    const float* __restrict__ g, const float* __restrict__ bt,
    float* __restrict__ outp)
{
    __shared__ float red[8];
    const int row = blockIdx.x;
    const int t   = threadIdx.x;
    const size_t off = (size_t)row * D2 + t * 4;

    float4 v = *(const float4*)(tmp2 + off);
    float s = v.x + v.y + v.z + v.w;
#pragma unroll
    for (int o = 16; o; o >>= 1) s += __shfl_xor_sync(0xffffffffu, s, o);
    if ((t & 31) == 0) red[t >> 5] = s;
    __syncthreads();
    const float mean = (red[0] + red[1] + red[2] + red[3]) * (1.0f / D2);

    float dx = v.x - mean, dy = v.y - mean, dz = v.z - mean, dw = v.w - mean;
    float s2 = dx * dx + dy * dy + dz * dz + dw * dw;
#pragma unroll
    for (int o = 16; o; o >>= 1) s2 += __shfl_xor_sync(0xffffffffu, s2, o);
    if ((t & 31) == 0) red[4 + (t >> 5)] = s2;
    __syncthreads();
    const float var  = (red[4] + red[5] + red[6] + red[7]) * (1.0f / D2);
    const float rstd = rsqrtf(var + EPS);

    float4 xv = *(const float4*)(x1 + off);
    float4 gg = *(const float4*)(g + t * 4);
    float4 bb = *(const float4*)(bt + t * 4);
    float4 o4;
    o4.x = xv.x + dx * rstd * gg.x + bb.x;
    o4.y = xv.y + dy * rstd * gg.y + bb.y;
    o4.z = xv.z + dz * rstd * gg.z + bb.z;
    o4.w = xv.w + dw * rstd * gg.w + bb.w;
    *(float4*)(outp + off) = o4;
}

// ---------------- host launch ------------------------------------------------
extern "C" void kernel_launch(void* const* d_in, const int* in_sizes, int n_in,
                              void* d_out, int out_size)
{
    const float* x1        = (const float*)d_in[0];
    const float* x2        = (const float*)d_in[1];
    const float* linear_w  = (const float*)d_in[2];
    const float* linear_b  = (const float*)d_in[3];
    const float* ln1_g     = (const float*)d_in[4];
    const float* ln1_b     = (const float*)d_in[5];
    const float* reproj_w  = (const float*)d_in[6];
    const float* reproj_b  = (const float*)d_in[7];
    const float* ln_attn_g = (const float*)d_in[8];
    const float* ln_attn_b = (const float*)d_in[9];
    float* out = (float*)d_out;

    float *tmp1, *n1, *n2, *tmp2, *part, *ksum, *Spart, *ctx;
    __nv_bfloat16 *w1h, *w1l, *b2h, *b2l;
    cudaGetSymbolAddress((void**)&tmp1, g_tmp1);
    cudaGetSymbolAddress((void**)&n1,   g_n1);
    cudaGetSymbolAddress((void**)&n2,   g_n2);
    cudaGetSymbolAddress((void**)&tmp2, g_tmp2);
    cudaGetSymbolAddress((void**)&w1h,  g_w1h);
    cudaGetSymbolAddress((void**)&w1l,  g_w1l);
    cudaGetSymbolAddress((void**)&b2h,  g_b2h);
    cudaGetSymbolAddress((void**)&b2l,  g_b2l);
    cudaGetSymbolAddress((void**)&part, g_part);
    cudaGetSymbolAddress((void**)&ksum, g_ksum);
    cudaGetSymbolAddress((void**)&Spart,g_Spart);
    cudaGetSymbolAddress((void**)&ctx,  g_ctx);

    cudaFuncSetAttribute(w2eff_k, cudaFuncAttributeMaxDynamicSharedMemorySize,
                         65536);

    // prep: W1 transpose/split + LN(x2)
    convert_w1_k<<<dim3(DD / 32, D2 / 32), dim3(32, 8)>>>(linear_w, w1h, w1l);
    ln_k<<<RR / 8, 256>>>(x2, ln1_g, ln1_b, n2);

    // GEMM1: tmp1 = x1 @ W1 + b1   (M=RR, N=256, K=512)
    mma_gemm_k<<<dim3(DD / 128, RR / 128), 256>>>(x1, w1h, w1l, linear_b,
                                                  tmp1, D2, DD, RR, 0);
    ln_k<<<RR / 8, 256>>>(tmp1, ln1_g, ln1_b, n1);

    // attention statistics
    ctx_part_k<<<dim3(8, HEADS, Bb), 256>>>(n2, Spart, part);
    ksum_reduce_k<<<Bb, DD>>>(part, ksum);
    ctx_final_k<<<Bb * HEADS, DK * DK>>>(Spart, ksum, ctx);

    // effective reprojection weights per batch
    w2eff_k<<<dim3(Bb, D2 / 32), 256, 65536>>>(ctx, reproj_w, b2h, b2l);

    // GEMM2: tmp2 = n1 @ W2eff[b] + reproj_b   (M=RR, N=512, K=256)
    mma_gemm_k<<<dim3(D2 / 128, RR / 128), 256>>>(n1, b2h, b2l, reproj_b,
                                                  tmp2, DD, D2, NN, D2 * DD);

    // out = x1 + LN(tmp2)
    final_ln_add_k<<<RR, 128>>>(tmp2, x1, ln_attn_g, ln_attn_b, out);
}

// round 5
// speedup vs baseline: 2.5676x; 1.3043x over previous
#include <cuda_runtime.h>
#include <cuda_fp16.h>
#include <cstdint>
#include <math.h>

#define Bb     8
#define NN     4096
#define RR     32768
#define DD     256
#define D2     512
#define HEADS  8
#define DK     32
#define EPS    1e-5f

// ---------------- scratch (device globals; no runtime allocation) -----------
__device__ __align__(16) float  g_tmp1[RR * DD];
__device__ __align__(16) __half g_n1h [RR * DD];
__device__ __align__(16) float  g_n2  [RR * DD];
__device__ __align__(16) float  g_tmp2[RR * D2];
__device__ __align__(16) __half g_w1h [DD * D2];       // W1^T [n][k] fp16
__device__ __align__(16) __half g_b2h [Bb * D2 * DD];  // W2eff [b][o][c] fp16
__device__ __align__(16) float  g_part [Bb * 8 * DD];
__device__ __align__(16) float  g_ksum [Bb * DD];
__device__ __align__(16) float  g_Spart[8 * Bb * HEADS * DK * DK];
__device__ __align__(16) float  g_ctx  [Bb * HEADS * DK * DK];

// ---------------- helpers ----------------------------------------------------
__device__ __forceinline__ uint32_t s2u(const void* p) {
    uint32_t a;
    asm("{ .reg .u64 t; cvta.to.shared.u64 t, %1; cvt.u32.u64 %0, t; }"
        : "=r"(a) : "l"(p));
    return a;
}

__device__ __forceinline__ void cvt8(const float4& a, const float4& b, uint4& o) {
    __half2 h0 = __floats2half2_rn(a.x, a.y);
    __half2 h1 = __floats2half2_rn(a.z, a.w);
    __half2 h2 = __floats2half2_rn(b.x, b.y);
    __half2 h3 = __floats2half2_rn(b.z, b.w);
    o.x = *reinterpret_cast<uint32_t*>(&h0);
    o.y = *reinterpret_cast<uint32_t*>(&h1);
    o.z = *reinterpret_cast<uint32_t*>(&h2);
    o.w = *reinterpret_cast<uint32_t*>(&h3);
}

// A-tile loaders: 16 contiguous K-elements -> 2x uint4 of fp16
__device__ __forceinline__ void ldA16(const float* p, uint4& r0, uint4& r1) {
    float4 a0 = *(const float4*)p;
    float4 a1 = *(const float4*)(p + 4);
    float4 a2 = *(const float4*)(p + 8);
    float4 a3 = *(const float4*)(p + 12);
    cvt8(a0, a1, r0);
    cvt8(a2, a3, r1);
}
__device__ __forceinline__ void ldA16(const __half* p, uint4& r0, uint4& r1) {
    r0 = *(const uint4*)p;
    r1 = *(const uint4*)(p + 8);
}

__device__ __forceinline__ void ldsm4(uint32_t* r, uint32_t addr) {
    asm volatile("ldmatrix.sync.aligned.m8n8.x4.shared.b16 {%0,%1,%2,%3}, [%4];"
                 : "=r"(r[0]), "=r"(r[1]), "=r"(r[2]), "=r"(r[3]) : "r"(addr));
}
__device__ __forceinline__ void mma16816(float* c, const uint32_t* a,
                                         const uint32_t* b) {
    asm volatile(
        "mma.sync.aligned.m16n8k16.row.col.f32.f16.f16.f32 "
        "{%0,%1,%2,%3}, {%4,%5,%6,%7}, {%8,%9}, {%0,%1,%2,%3};"
        : "+f"(c[0]), "+f"(c[1]), "+f"(c[2]), "+f"(c[3])
        : "r"(a[0]), "r"(a[1]), "r"(a[2]), "r"(a[3]), "r"(b[0]), "r"(b[1]));
}

// swizzled byte offset: rows of 32 fp16 (64B), 4 chunks of 16B, XOR swizzle
__device__ __forceinline__ uint32_t sw_off(int row, int cch) {
    return (uint32_t)(row * 64 + ((cch ^ ((row >> 1) & 3)) << 4));
}

// ---------------- fp16 HMMA GEMM --------------------------------------------
// C[M,N] = A[M,K] @ B[N,K](fp16 row-major n x k) + bias[N]
// CTA 128x128, 8 warps (2 m x 4 n), warp tile 64x32, KC=32.
template <typename AT>
__global__ __launch_bounds__(256, 2) void mma_gemm_k(
    const AT* __restrict__ A, const __half* __restrict__ B,
    const float* __restrict__ bias, float* __restrict__ C,
    int K, int N, int rows_per_batch, long bstride)
{
    __shared__ __align__(16) __half sA[128 * 32];
    __shared__ __align__(16) __half sB[128 * 32];

    const int t = threadIdx.x, lane = t & 31, wid = t >> 5;
    const int wm = (wid & 1) * 64;
    const int wn = (wid >> 1) * 32;
    const int row0 = blockIdx.y * 128, n0 = blockIdx.x * 128;
    const int b = row0 / rows_per_batch;
    const __half* Bp = B + (size_t)b * bstride;

    const uint32_t uA = s2u(sA), uB = s2u(sB);

    float acc[4][4][4];
#pragma unroll
    for (int i = 0; i < 4; i++)
#pragma unroll
        for (int j = 0; j < 4; j++)
#pragma unroll
            for (int k = 0; k < 4; k++) acc[i][j][k] = 0.f;

    const int ar = t >> 1, acol = (t & 1) * 16;
    const AT*     aptr = A  + (size_t)(row0 + ar) * K + acol;
    const __half* bptr = Bp + (size_t)(n0 + ar) * K + acol;
    const uint32_t sta0 = sw_off(ar, (acol >> 3));
    const uint32_t sta1 = sw_off(ar, (acol >> 3) + 1);

    const int ti = lane >> 3, tr = lane & 7;
    const int a_dm = (ti & 1) * 8, a_dkc = ti >> 1;
    const int b_dn = (ti >> 1) * 8, b_dkc = ti & 1;

    const int nk = K >> 5;
    for (int kk = 0; kk < nk; kk++) {
        const int k0 = kk << 5;
        uint4 a0, a1, b0, b1;
        ldA16(aptr + k0, a0, a1);
        b0 = *(const uint4*)(bptr + k0);
        b1 = *(const uint4*)(bptr + k0 + 8);

        __syncthreads();
        *(uint4*)((char*)sA + sta0) = a0;
        *(uint4*)((char*)sA + sta1) = a1;
        *(uint4*)((char*)sB + sta0) = b0;
        *(uint4*)((char*)sB + sta1) = b1;
        __syncthreads();

#pragma unroll
        for (int ks = 0; ks < 2; ks++) {
            uint32_t af[4][4], bf[2][4];
#pragma unroll
            for (int mf = 0; mf < 4; mf++) {
                const int row = wm + mf * 16 + a_dm + tr;
                ldsm4(af[mf], uA + sw_off(row, ks * 2 + a_dkc));
            }
#pragma unroll
            for (int g = 0; g < 2; g++) {
                const int row = wn + g * 16 + b_dn + tr;
                ldsm4(bf[g], uB + sw_off(row, ks * 2 + b_dkc));
            }
#pragma unroll
            for (int mf = 0; mf < 4; mf++)
#pragma unroll
                for (int nf = 0; nf < 4; nf++)
                    mma16816(acc[mf][nf], af[mf], &bf[nf >> 1][(nf & 1) * 2]);
        }
    }

    const int rbase = row0 + wm + (lane >> 2);
    const int cbase = n0 + wn + (lane & 3) * 2;
#pragma unroll
    for (int nf = 0; nf < 4; nf++) {
        const int c = cbase + nf * 8;
        const float bx = bias[c], by = bias[c + 1];
#pragma unroll
        for (int mf = 0; mf < 4; mf++) {
            const int r = rbase + mf * 16;
            float2 v0 = make_float2(acc[mf][nf][0] + bx, acc[mf][nf][1] + by);
            float2 v1 = make_float2(acc[mf][nf][2] + bx, acc[mf][nf][3] + by);
            *(float2*)(C + (size_t)r * N + c) = v0;
            *(float2*)(C + (size_t)(r + 8) * N + c) = v1;
        }
    }
}

// ---------------- warp-per-row LayerNorm over D=256 --------------------------
// computes LN; writes fp32 (dst32) or fp16 (dst16), whichever is non-null use.
__global__ __launch_bounds__(256) void ln_f32_k(
    const float* __restrict__ src, const float* __restrict__ g,
    const float* __restrict__ b, float* __restrict__ dst)
{
    const int row  = (blockIdx.x * blockDim.x + threadIdx.x) >> 5;
    const int lane = threadIdx.x & 31;
    const float* p = src + (size_t)row * DD + lane * 8;
    float4 a = *(const float4*)p;
    float4 c = *(const float4*)(p + 4);

    float s = a.x + a.y + a.z + a.w + c.x + c.y + c.z + c.w;
#pragma unroll
    for (int o = 16; o; o >>= 1) s += __shfl_xor_sync(0xffffffffu, s, o);
    const float mean = s * (1.0f / DD);

    float ax = a.x - mean, ay = a.y - mean, az = a.z - mean, aw = a.w - mean;
    float cx = c.x - mean, cy = c.y - mean, cz = c.z - mean, cw = c.w - mean;
    float s2 = ax*ax + ay*ay + az*az + aw*aw + cx*cx + cy*cy + cz*cz + cw*cw;
#pragma unroll
    for (int o = 16; o; o >>= 1) s2 += __shfl_xor_sync(0xffffffffu, s2, o);
    const float rstd = rsqrtf(s2 * (1.0f / DD) + EPS);

    const int ci = lane * 8;
    float4 g0 = *(const float4*)(g + ci);
    float4 g1 = *(const float4*)(g + ci + 4);
    float4 b0 = *(const float4*)(b + ci);
    float4 b1 = *(const float4*)(b + ci + 4);
    float4 o0, o1;
    o0.x = ax*rstd*g0.x + b0.x; o0.y = ay*rstd*g0.y + b0.y;
    o0.z = az*rstd*g0.z + b0.z; o0.w = aw*rstd*g0.w + b0.w;
    o1.x = cx*rstd*g1.x + b1.x; o1.y = cy*rstd*g1.y + b1.y;
    o1.z = cz*rstd*g1.z + b1.z; o1.w = cw*rstd*g1.w + b1.w;
    float* q = dst + (size_t)row * DD + ci;
    *(float4*)q       = o0;
    *(float4*)(q + 4) = o1;
}

__global__ __launch_bounds__(256) void ln_f16_k(
    const float* __restrict__ src, const float* __restrict__ g,
    const float* __restrict__ b, __half* __restrict__ dst)
{
    const int row  = (blockIdx.x * blockDim.x + threadIdx.x) >> 5;
    const int lane = threadIdx.x & 31;
    const float* p = src + (size_t)row * DD + lane * 8;
    float4 a = *(const float4*)p;
    float4 c = *(const float4*)(p + 4);

    float s = a.x + a.y + a.z + a.w + c.x + c.y + c.z + c.w;
#pragma unroll
    for (int o = 16; o; o >>= 1) s += __shfl_xor_sync(0xffffffffu, s, o);
    const float mean = s * (1.0f / DD);

    float ax = a.x - mean, ay = a.y - mean, az = a.z - mean, aw = a.w - mean;
    float cx = c.x - mean, cy = c.y - mean, cz = c.z - mean, cw = c.w - mean;
    float s2 = ax*ax + ay*ay + az*az + aw*aw + cx*cx + cy*cy + cz*cz + cw*cw;
#pragma unroll
    for (int o = 16; o; o >>= 1) s2 += __shfl_xor_sync(0xffffffffu, s2, o);
    const float rstd = rsqrtf(s2 * (1.0f / DD) + EPS);

    const int ci = lane * 8;
    float4 g0 = *(const float4*)(g + ci);
    float4 g1 = *(const float4*)(g + ci + 4);
    float4 b0 = *(const float4*)(b + ci);
    float4 b1 = *(const float4*)(b + ci + 4);
    float4 o0, o1;
    o0.x = ax*rstd*g0.x + b0.x; o0.y = ay*rstd*g0.y + b0.y;
    o0.z = az*rstd*g0.z + b0.z; o0.w = aw*rstd*g0.w + b0.w;
    o1.x = cx*rstd*g1.x + b1.x; o1.y = cy*rstd*g1.y + b1.y;
    o1.z = cz*rstd*g1.z + b1.z; o1.w = cw*rstd*g1.w + b1.w;

    uint4 ov;
    cvt8(o0, o1, ov);
    *(uint4*)(dst + (size_t)row * DD + ci) = ov;
}

// ---------------- ctx partials + fused ksum partials -------------------------
__global__ __launch_bounds__(256) void ctx_part_k(
    const float* __restrict__ n2, float* __restrict__ Spart,
    float* __restrict__ part)
{
    __shared__ __align__(16) float sm_e[2][8][32];
    __shared__ __align__(16) float sm_q[2][8][32];
    __shared__ float sred[8][32];

    const int chunk = blockIdx.x;   // 8
    const int h     = blockIdx.y;   // 8
    const int b     = blockIdx.z;   // 8
    const int t     = threadIdx.x;
    const int lane  = t & 31;
    const int w     = t >> 5;
    const int tx    = t & 15;
    const int ty    = t >> 4;

    float a00 = 0.f, a01 = 0.f, a10 = 0.f, a11 = 0.f, ks = 0.f;
    const float* base = n2 + ((size_t)b * NN + chunk * 512) * DD + h * DK;

    for (int nb = 0; nb < 512; nb += 8) {
        const int p = (nb >> 3) & 1;
        float e = __expf(base[(size_t)(nb + w) * DD + lane]);
        ks += e;
        float qs = e;
#pragma unroll
        for (int o = 16; o; o >>= 1) qs += __shfl_xor_sync(0xffffffffu, qs, o);
        sm_e[p][w][lane] = e;
        sm_q[p][w][lane] = e / qs;
        __syncthreads();
#pragma unroll
        for (int j = 0; j < 8; j++) {
            float2 qd = *(const float2*)&sm_q[p][j][ty * 2];
            float2 ke = *(const float2*)&sm_e[p][j][tx * 2];
            a00 += qd.x * ke.x; a01 += qd.x * ke.y;
            a10 += qd.y * ke.x; a11 += qd.y * ke.y;
        }
    }

    sred[w][lane] = ks;
    __syncthreads();
    if (t < 32) {
        float s = 0.f;
#pragma unroll
        for (int j = 0; j < 8; j++) s += sred[j][t];
        part[(b * 8 + chunk) * DD + h * DK + t] = s;
    }

    float* o = Spart + (size_t)(chunk * 64 + b * 8 + h) * (DK * DK);
    const int d = ty * 2, e = tx * 2;
    o[d * 32 + e]           = a00;
    o[d * 32 + e + 1]       = a01;
    o[(d + 1) * 32 + e]     = a10;
    o[(d + 1) * 32 + e + 1] = a11;
}

__global__ void ksum_reduce_k(const float* __restrict__ part,
                              float* __restrict__ ksum)
{
    const int b = blockIdx.x, c = threadIdx.x;
    float s = 0.f;
#pragma unroll
    for (int j = 0; j < 8; j++) s += part[(b * 8 + j) * DD + c];
    ksum[b * DD + c] = s;
}

__global__ __launch_bounds__(1024) void ctx_final_k(
    const float* __restrict__ Spart, const float* __restrict__ ksum,
    float* __restrict__ ctx)
{
    const int bh = blockIdx.x;
    const int t  = threadIdx.x;   // d*32+e
    const int b  = bh >> 3, h = bh & 7;
    const int e  = t & 31;
    float s = 0.f;
#pragma unroll
    for (int ch = 0; ch < 8; ch++)
        s += Spart[(size_t)(ch * 64 + bh) * (DK * DK) + t];
    ctx[(size_t)bh * (DK * DK) + t] = s / ksum[b * DD + h * DK + e];
}

// ---------------- W2eff[b][o][c=h*32+e] = sum_d ctx[b,h,d,e]*rw[o][h*32+d] ---
__global__ __launch_bounds__(256) void w2eff_k(
    const float* __restrict__ ctx, const float* __restrict__ rw,
    __half* __restrict__ b2h)
{
    extern __shared__ float ws[];
    float* ctxs = ws;          // 8192
    float* rws  = ws + 8192;   // 32 x 256
    const int b  = blockIdx.x;
    const int o0 = blockIdx.y * 32;
    const int t  = threadIdx.x;

    const float* cs = ctx + (size_t)b * HEADS * DK * DK;
    for (int i = t; i < HEADS * DK * DK; i += 256) ctxs[i] = cs[i];
    for (int i = t; i < 32 * 256; i += 256)
        rws[i] = rw[(size_t)(o0 + (i >> 8)) * DD + (i & 255)];
    __syncthreads();

    const int h = t >> 5, e = t & 31;
    const float* cbase = ctxs + h * (DK * DK) + e;
    for (int o = 0; o < 32; o++) {
        float acc = 0.f;
        const float* rb = rws + (o << 8) + h * DK;
#pragma unroll
        for (int d = 0; d < 32; d++) acc += cbase[d * 32] * rb[d];
        b2h[((size_t)b * D2 + o0 + o) * DD + t] = __float2half_rn(acc);
    }
}

// ---------------- W1 transpose + fp16 conversion -----------------------------
__global__ void convert_w1_k(const float* __restrict__ W,
                             __half* __restrict__ wh)
{
    __shared__ float tile[32][33];
    const int n0 = blockIdx.x * 32;   // DD cols of W
    const int k0 = blockIdx.y * 32;   // D2 rows of W
    const int x = threadIdx.x, y = threadIdx.y;  // 32x8
#pragma unroll
    for (int i = 0; i < 32; i += 8)
        tile[y + i][x] = W[(size_t)(k0 + y + i) * DD + n0 + x];
    __syncthreads();
#pragma unroll
    for (int i = 0; i < 32; i += 8)
        wh[(size_t)(n0 + y + i) * D2 + k0 + x] = __float2half_rn(tile[x][y + i]);
}

// ---------------- final LN(512) + residual add -------------------------------
__global__ __launch_bounds__(128) void final_ln_add_k(
    const float* __restrict__ tmp2, const float* __restrict__ x1,
    const float* __restrict__ g, const float* __restrict__ bt,
    float* __restrict__ outp)
{
    __shared__ float red[8];
    const int row = blockIdx.x;
    const int t   = threadIdx.x;
    const size_t off = (size_t)row * D2 + t * 4;

    float4 v = *(const float4*)(tmp2 + off);
    float s = v.x + v.y + v.z + v.w;
#pragma unroll
    for (int o = 16; o; o >>= 1) s += __shfl_xor_sync(0xffffffffu, s, o);
    if ((t & 31) == 0) red[t >> 5] = s;
    __syncthreads();
    const float mean = (red[0] + red[1] + red[2] + red[3]) * (1.0f / D2);

    float dx = v.x - mean, dy = v.y - mean, dz = v.z - mean, dw = v.w - mean;
    float s2 = dx * dx + dy * dy + dz * dz + dw * dw;
#pragma unroll
    for (int o = 16; o; o >>= 1) s2 += __shfl_xor_sync(0xffffffffu, s2, o);
    if ((t & 31) == 0) red[4 + (t >> 5)] = s2;
    __syncthreads();
    const float var  = (red[4] + red[5] + red[6] + red[7]) * (1.0f / D2);
    const float rstd = rsqrtf(var + EPS);

    float4 xv = *(const float4*)(x1 + off);
    float4 gg = *(const float4*)(g + t * 4);
    float4 bb = *(const float4*)(bt + t * 4);
    float4 o4;
    o4.x = xv.x + dx * rstd * gg.x + bb.x;
    o4.y = xv.y + dy * rstd * gg.y + bb.y;
    o4.z = xv.z + dz * rstd * gg.z + bb.z;
    o4.w = xv.w + dw * rstd * gg.w + bb.w;
    *(float4*)(outp + off) = o4;
}

// ---------------- host launch ------------------------------------------------
extern "C" void kernel_launch(void* const* d_in, const int* in_sizes, int n_in,
                              void* d_out, int out_size)
{
    const float* x1        = (const float*)d_in[0];
    const float* x2        = (const float*)d_in[1];
    const float* linear_w  = (const float*)d_in[2];
    const float* linear_b  = (const float*)d_in[3];
    const float* ln1_g     = (const float*)d_in[4];
    const float* ln1_b     = (const float*)d_in[5];
    const float* reproj_w  = (const float*)d_in[6];
    const float* reproj_b  = (const float*)d_in[7];
    const float* ln_attn_g = (const float*)d_in[8];
    const float* ln_attn_b = (const float*)d_in[9];
    float* out = (float*)d_out;

    float *tmp1, *n2, *tmp2, *part, *ksum, *Spart, *ctx;
    __half *n1h, *w1h, *b2h;
    cudaGetSymbolAddress((void**)&tmp1, g_tmp1);
    cudaGetSymbolAddress((void**)&n1h,  g_n1h);
    cudaGetSymbolAddress((void**)&n2,   g_n2);
    cudaGetSymbolAddress((void**)&tmp2, g_tmp2);
    cudaGetSymbolAddress((void**)&w1h,  g_w1h);
    cudaGetSymbolAddress((void**)&b2h,  g_b2h);
    cudaGetSymbolAddress((void**)&part, g_part);
    cudaGetSymbolAddress((void**)&ksum, g_ksum);
    cudaGetSymbolAddress((void**)&Spart,g_Spart);
    cudaGetSymbolAddress((void**)&ctx,  g_ctx);

    cudaFuncSetAttribute(w2eff_k, cudaFuncAttributeMaxDynamicSharedMemorySize,
                         65536);

    // prep: W1 transpose/convert + LN(x2)
    convert_w1_k<<<dim3(DD / 32, D2 / 32), dim3(32, 8)>>>(linear_w, w1h);
    ln_f32_k<<<RR / 8, 256>>>(x2, ln1_g, ln1_b, n2);

    // GEMM1: tmp1 = x1 @ W1 + b1   (M=RR, N=256, K=512)
    mma_gemm_k<float><<<dim3(DD / 128, RR / 128), 256>>>(
        x1, w1h, linear_b, tmp1, D2, DD, RR, 0);
    ln_f16_k<<<RR / 8, 256>>>(tmp1, ln1_g, ln1_b, n1h);

    // attention statistics
    ctx_part_k<<<dim3(8, HEADS, Bb), 256>>>(n2, Spart, part);
    ksum_reduce_k<<<Bb, DD>>>(part, ksum);
    ctx_final_k<<<Bb * HEADS, DK * DK>>>(Spart, ksum, ctx);

    // effective reprojection weights per batch
    w2eff_k<<<dim3(Bb, D2 / 32), 256, 65536>>>(ctx, reproj_w, b2h);

    // GEMM2: tmp2 = n1 @ W2eff[b] + reproj_b   (M=RR, N=512, K=256)
    mma_gemm_k<__half><<<dim3(D2 / 128, RR / 128), 256>>>(
        n1h, b2h, reproj_b, tmp2, DD, D2, NN, (long)D2 * DD);

    // out = x1 + LN(tmp2)
    final_ln_add_k<<<RR, 128>>>(tmp2, x1, ln_attn_g, ln_attn_b, out);
}